// round 1
// baseline (speedup 1.0000x reference)
#include <cuda_runtime.h>

#define Bn 4
#define Ln 200
#define Hn 256
#define NHn 4
#define HSn 64

// scratch: Q, Kc = K + abs_pos_K, Vc = V + abs_pos_V   (each 0.82 MB)
__device__ float g_Q [Bn * Ln * Hn];
__device__ float g_Kc[Bn * Ln * Hn];
__device__ float g_Vc[Bn * Ln * Hn];

#define PROJ_ROWS 8

// ---------------------------------------------------------------------------
// Projection kernel: Q = x@Qw^T+Qb ; Kc = k@Kw^T+Kb+pK ; Vc = k@Vw^T+Vb+pV
// One CTA per 8 rows; thread j owns output column j and streams W rows once,
// reusing them across 8 input rows (8x L2 traffic reduction on weights).
// ---------------------------------------------------------------------------
__global__ __launch_bounds__(256)
void proj_kernel(const float* __restrict__ queries,
                 const float* __restrict__ keys,
                 const float* __restrict__ apK,
                 const float* __restrict__ apV,
                 const float* __restrict__ Qw, const float* __restrict__ Qb,
                 const float* __restrict__ Kw, const float* __restrict__ Kb,
                 const float* __restrict__ Vw, const float* __restrict__ Vb)
{
    __shared__ float xq[PROJ_ROWS][Hn];
    __shared__ float xk[PROJ_ROWS][Hn];
    const int r0 = blockIdx.x * PROJ_ROWS;
    const int t  = threadIdx.x;

    #pragma unroll
    for (int r = 0; r < PROJ_ROWS; ++r) {
        xq[r][t] = queries[(r0 + r) * Hn + t];
        xk[r][t] = keys   [(r0 + r) * Hn + t];
    }
    __syncthreads();

    const int j = t;
    float accq[PROJ_ROWS], acck[PROJ_ROWS], accv[PROJ_ROWS];
    #pragma unroll
    for (int r = 0; r < PROJ_ROWS; ++r) { accq[r] = 0.f; acck[r] = 0.f; accv[r] = 0.f; }

    const float* __restrict__ qw = Qw + (size_t)j * Hn;
    const float* __restrict__ kw = Kw + (size_t)j * Hn;
    const float* __restrict__ vw = Vw + (size_t)j * Hn;

    #pragma unroll 4
    for (int i = 0; i < Hn; ++i) {
        const float wq = qw[i], wk = kw[i], wv = vw[i];
        #pragma unroll
        for (int r = 0; r < PROJ_ROWS; ++r) {
            accq[r] += xq[r][i] * wq;
            acck[r] += xk[r][i] * wk;
            accv[r] += xk[r][i] * wv;
        }
    }

    const float bq = Qb[j], bk = Kb[j], bv = Vb[j];
    #pragma unroll
    for (int r = 0; r < PROJ_ROWS; ++r) {
        const int row = r0 + r;
        g_Q [row * Hn + j] = accq[r] + bq;
        g_Kc[row * Hn + j] = acck[r] + bk + apK[row * Hn + j];
        g_Vc[row * Hn + j] = accv[r] + bv + apV[row * Hn + j];
    }
}

// ---------------------------------------------------------------------------
// Main attention kernel: one CTA per (b, l) query row.
// 256 threads = 4 key-rows in flight (msub 0..3) x 64 float4 lanes (qd).
// Causal: only m <= l is ever touched in HBM (masked weights are exactly 0).
// ---------------------------------------------------------------------------
__global__ __launch_bounds__(256)
void attn_kernel(const float4* __restrict__ tK, const float4* __restrict__ tV,
                 const float4* __restrict__ dK, const float4* __restrict__ dV,
                 const unsigned char* __restrict__ time_mask,
                 float4* __restrict__ out)
{
    const int bx = blockIdx.x;
    const int b  = bx % Bn;
    const int l  = (Ln - 1) - bx / Bn;        // heavy rows first
    const int t    = threadIdx.x;
    const int msub = t >> 6;                   // which of the 4 concurrent key rows
    const int qd   = t & 63;                   // float4 index within the 256-float row
    const int head = qd >> 4;                  // 16 float4 lanes per head

    __shared__ float  sW[NHn][Ln];             // logits, then softmax weights
    __shared__ float4 sRed[4][64];
    __shared__ float  qsh[Hn];

    qsh[t] = g_Q[(size_t)(b * Ln + l) * Hn + t];
    __syncthreads();
    const float4 qv = *reinterpret_cast<const float4*>(&qsh[qd * 4]);

    const bool tm   = time_mask[b * Ln + l] != 0;
    const int  mEnd = tm ? Ln : (l + 1);

    const float4* __restrict__ Kc4 = reinterpret_cast<const float4*>(g_Kc);
    const float4* __restrict__ Vc4 = reinterpret_cast<const float4*>(g_Vc);
    const size_t rowBase = ((size_t)(b * Ln + l)) * Ln;   // row index into [B,L,L] grid

    if (!tm) {
        // ---- pass 1: logits  w[h][m] = q . (Kc + tK + dK) ----
        for (int m0 = 0; m0 < mEnd; m0 += 4) {
            const int m = m0 + msub;
            float s = 0.f;
            if (m < mEnd) {
                const size_t off = (rowBase + (size_t)m) * 64 + qd;
                const float4 a = tK[off];
                const float4 c = dK[off];
                const float4 k = Kc4[(size_t)(b * Ln + m) * 64 + qd];
                s = qv.x * (a.x + c.x + k.x) + qv.y * (a.y + c.y + k.y)
                  + qv.z * (a.z + c.z + k.z) + qv.w * (a.w + c.w + k.w);
            }
            // reduce across the 16 lanes of this head (stays inside a warp)
            s += __shfl_xor_sync(0xffffffffu, s, 8);
            s += __shfl_xor_sync(0xffffffffu, s, 4);
            s += __shfl_xor_sync(0xffffffffu, s, 2);
            s += __shfl_xor_sync(0xffffffffu, s, 1);
            if (m < mEnd && (qd & 15) == 0)
                sW[head][m] = s;
        }
        __syncthreads();

        // ---- pass 2: softmax, one warp per head ----
        if (t < 128) {
            const int h    = t >> 5;
            const int lane = t & 31;
            float mx = -3.4e38f;
            for (int m = lane; m < mEnd; m += 32) mx = fmaxf(mx, sW[h][m]);
            #pragma unroll
            for (int o = 16; o; o >>= 1) mx = fmaxf(mx, __shfl_xor_sync(0xffffffffu, mx, o));
            float sum = 0.f;
            for (int m = lane; m < mEnd; m += 32) {
                const float e = __expf(0.125f * (sW[h][m] - mx));   // 1/sqrt(64)
                sW[h][m] = e;
                sum += e;
            }
            #pragma unroll
            for (int o = 16; o; o >>= 1) sum += __shfl_xor_sync(0xffffffffu, sum, o);
            const float inv = 1.f / sum;
            for (int m = lane; m < mEnd; m += 32) sW[h][m] *= inv;
        }
    } else {
        // all logits are NEG -> softmax is uniform over the full row
        const float u = 1.f / (float)Ln;
        for (int m = t; m < Ln; m += 256) {
            sW[0][m] = u; sW[1][m] = u; sW[2][m] = u; sW[3][m] = u;
        }
    }
    __syncthreads();

    // ---- pass 3: out = sum_m a[h][m] * (Vc + tV + dV) ----
    float4 acc = make_float4(0.f, 0.f, 0.f, 0.f);
    for (int m0 = 0; m0 < mEnd; m0 += 4) {
        const int m = m0 + msub;
        if (m < mEnd) {
            const float  a   = sW[head][m];
            const size_t off = (rowBase + (size_t)m) * 64 + qd;
            const float4 x = tV[off];
            const float4 y = dV[off];
            const float4 v = Vc4[(size_t)(b * Ln + m) * 64 + qd];
            acc.x += a * (x.x + y.x + v.x);
            acc.y += a * (x.y + y.y + v.y);
            acc.z += a * (x.z + y.z + v.z);
            acc.w += a * (x.w + y.w + v.w);
        }
    }
    sRed[msub][qd] = acc;
    __syncthreads();
    if (msub == 0) {
        const float4 r0 = sRed[0][qd], r1 = sRed[1][qd], r2 = sRed[2][qd], r3 = sRed[3][qd];
        float4 o;
        o.x = r0.x + r1.x + r2.x + r3.x;
        o.y = r0.y + r1.y + r2.y + r3.y;
        o.z = r0.z + r1.z + r2.z + r3.z;
        o.w = r0.w + r1.w + r2.w + r3.w;
        out[(size_t)(b * Ln + l) * 64 + qd] = o;
    }
}

// ---------------------------------------------------------------------------
// Input order (setup_inputs): 0 queries, 1 keys, 2 time_matrix_K,
// 3 time_matrix_V, 4 dis_matrix_K, 5 dis_matrix_V, 6 abs_pos_K, 7 abs_pos_V,
// 8 Qw, 9 Qb, 10 Kw, 11 Kb, 12 Vw, 13 Vb, 14 time_mask, 15 attn_mask (causal,
// structural -> handled analytically).
// ---------------------------------------------------------------------------
extern "C" void kernel_launch(void* const* d_in, const int* in_sizes, int n_in,
                              void* d_out, int out_size)
{
    const float* queries = (const float*)d_in[0];
    const float* keys    = (const float*)d_in[1];
    const float4* tK     = (const float4*)d_in[2];
    const float4* tV     = (const float4*)d_in[3];
    const float4* dK     = (const float4*)d_in[4];
    const float4* dV     = (const float4*)d_in[5];
    const float* apK     = (const float*)d_in[6];
    const float* apV     = (const float*)d_in[7];
    const float* Qw      = (const float*)d_in[8];
    const float* Qb      = (const float*)d_in[9];
    const float* Kw      = (const float*)d_in[10];
    const float* Kb      = (const float*)d_in[11];
    const float* Vw      = (const float*)d_in[12];
    const float* Vb      = (const float*)d_in[13];
    const unsigned char* time_mask = (const unsigned char*)d_in[14];

    proj_kernel<<<(Bn * Ln) / PROJ_ROWS, 256>>>(queries, keys, apK, apV,
                                                Qw, Qb, Kw, Kb, Vw, Vb);
    attn_kernel<<<Bn * Ln, 256>>>(tK, tV, dK, dV, time_mask, (float4*)d_out);
}

// round 2
// speedup vs baseline: 1.6880x; 1.6880x over previous
#include <cuda_runtime.h>

#define Bn 4
#define Ln 200
#define Hn 256
#define NHn 4
#define HSn 64

// scratch (float4-aligned): Q, Kc = K+abs_pos_K, Vc = V+abs_pos_V
__device__ float4 g_Q4 [Bn * Ln * (Hn / 4)];
__device__ float4 g_Kc4[Bn * Ln * (Hn / 4)];
__device__ float4 g_Vc4[Bn * Ln * (Hn / 4)];

#define PROJ_ROWS 8
#define KC 8

// ---------------------------------------------------------------------------
// Projection: Q = x@Qw^T+Qb ; Kc = k@Kw^T+Kb+pK ; Vc = k@Vw^T+Vb+pV
// W chunks staged through smem, TRANSPOSED (ws[ii][j]) so gmem loads are
// coalesced (warp reads contiguous row segments) and compute-side smem reads
// (ws[ii][t]) are conflict-free. Row stride 257 breaks write-bank alignment.
// ---------------------------------------------------------------------------
__global__ __launch_bounds__(256)
void proj_kernel(const float* __restrict__ queries,
                 const float* __restrict__ keys,
                 const float* __restrict__ apK,
                 const float* __restrict__ apV,
                 const float* __restrict__ Qw, const float* __restrict__ Qb,
                 const float* __restrict__ Kw, const float* __restrict__ Kb,
                 const float* __restrict__ Vw, const float* __restrict__ Vb)
{
    __shared__ float xq[PROJ_ROWS][Hn];
    __shared__ float xk[PROJ_ROWS][Hn];
    __shared__ float wq[KC][257], wk[KC][257], wv[KC][257];

    const int r0 = blockIdx.x * PROJ_ROWS;
    const int t  = threadIdx.x;

    #pragma unroll
    for (int r = 0; r < PROJ_ROWS; ++r) {
        xq[r][t] = queries[(r0 + r) * Hn + t];
        xk[r][t] = keys   [(r0 + r) * Hn + t];
    }

    float accq[PROJ_ROWS], acck[PROJ_ROWS], accv[PROJ_ROWS];
    #pragma unroll
    for (int r = 0; r < PROJ_ROWS; ++r) { accq[r] = 0.f; acck[r] = 0.f; accv[r] = 0.f; }

    for (int i0 = 0; i0 < Hn; i0 += KC) {
        __syncthreads();
        #pragma unroll
        for (int u = 0; u < KC; ++u) {
            const int idx = t + u * 256;           // 0 .. 256*KC-1
            const int j   = idx >> 3;              // weight row (output col)
            const int ii  = idx & (KC - 1);        // position in chunk
            wq[ii][j] = Qw[j * Hn + i0 + ii];
            wk[ii][j] = Kw[j * Hn + i0 + ii];
            wv[ii][j] = Vw[j * Hn + i0 + ii];
        }
        __syncthreads();
        #pragma unroll
        for (int ii = 0; ii < KC; ++ii) {
            const float aq = wq[ii][t], ak = wk[ii][t], av = wv[ii][t];
            #pragma unroll
            for (int r = 0; r < PROJ_ROWS; ++r) {
                const float xqv = xq[r][i0 + ii];
                const float xkv = xk[r][i0 + ii];
                accq[r] += xqv * aq;
                acck[r] += xkv * ak;
                accv[r] += xkv * av;
            }
        }
    }

    const float bq = Qb[t], bk = Kb[t], bv = Vb[t];
    float* gQ  = (float*)g_Q4;
    float* gKc = (float*)g_Kc4;
    float* gVc = (float*)g_Vc4;
    #pragma unroll
    for (int r = 0; r < PROJ_ROWS; ++r) {
        const int row = r0 + r;
        gQ [row * Hn + t] = accq[r] + bq;
        gKc[row * Hn + t] = acck[r] + bk + apK[row * Hn + t];
        gVc[row * Hn + t] = accv[r] + bv + apV[row * Hn + t];
    }
}

// ---------------------------------------------------------------------------
// Attention: one CTA per (b, row-pair). Pairing l and L-1-l makes per-CTA
// causal work exactly L+1 key-rows -> perfectly balanced grid, no tail.
// 512 threads = 8 key-rows in flight x 64 float4 lanes.
// ---------------------------------------------------------------------------
__global__ __launch_bounds__(512)
void attn_kernel(const float4* __restrict__ tK, const float4* __restrict__ tV,
                 const float4* __restrict__ dK, const float4* __restrict__ dV,
                 const unsigned char* __restrict__ time_mask,
                 float4* __restrict__ out)
{
    const int bx = blockIdx.x;               // 0..399
    const int b  = bx & (Bn - 1);
    const int p  = bx >> 2;                  // 0..99
    const int t    = threadIdx.x;
    const int msub = t >> 6;                 // 0..7: which concurrent key row
    const int qd   = t & 63;                 // float4 lane within 256-float row
    const int head = qd >> 4;

    __shared__ float  sW[NHn][Ln];
    __shared__ float4 sRed[8][64];
    __shared__ float  qsh[Hn];

    const float4* __restrict__ Kc4 = g_Kc4;
    const float4* __restrict__ Vc4 = g_Vc4;
    const float*  __restrict__ gQ  = (const float*)g_Q4;

    #pragma unroll 1
    for (int rr = 0; rr < 2; ++rr) {
        const int l = rr ? p : (Ln - 1 - p);   // heavy row first

        if (t < Hn) qsh[t] = gQ[(size_t)(b * Ln + l) * Hn + t];
        __syncthreads();
        const float4 qv = *reinterpret_cast<const float4*>(&qsh[qd * 4]);

        const bool tm   = time_mask[b * Ln + l] != 0;
        const int  mEnd = tm ? Ln : (l + 1);
        const size_t rowBase = ((size_t)(b * Ln + l)) * Ln;

        if (!tm) {
            // ---- pass 1: logits ----
            #pragma unroll 2
            for (int m0 = 0; m0 < mEnd; m0 += 8) {
                const int m = m0 + msub;
                float s = 0.f;
                if (m < mEnd) {
                    const size_t off = (rowBase + (size_t)m) * 64 + qd;
                    const float4 a = tK[off];
                    const float4 c = dK[off];
                    const float4 k = Kc4[(size_t)(b * Ln + m) * 64 + qd];
                    s = qv.x * (a.x + c.x + k.x) + qv.y * (a.y + c.y + k.y)
                      + qv.z * (a.z + c.z + k.z) + qv.w * (a.w + c.w + k.w);
                }
                s += __shfl_xor_sync(0xffffffffu, s, 8);
                s += __shfl_xor_sync(0xffffffffu, s, 4);
                s += __shfl_xor_sync(0xffffffffu, s, 2);
                s += __shfl_xor_sync(0xffffffffu, s, 1);
                if (m < mEnd && (qd & 15) == 0)
                    sW[head][m] = s;
            }
            __syncthreads();

            // ---- pass 2: softmax, one warp per head ----
            if (t < 128) {
                const int h    = t >> 5;
                const int lane = t & 31;
                float mx = -3.4e38f;
                for (int m = lane; m < mEnd; m += 32) mx = fmaxf(mx, sW[h][m]);
                #pragma unroll
                for (int o = 16; o; o >>= 1) mx = fmaxf(mx, __shfl_xor_sync(0xffffffffu, mx, o));
                float sum = 0.f;
                for (int m = lane; m < mEnd; m += 32) {
                    const float e = __expf(0.125f * (sW[h][m] - mx));  // 1/sqrt(64)
                    sW[h][m] = e;
                    sum += e;
                }
                #pragma unroll
                for (int o = 16; o; o >>= 1) sum += __shfl_xor_sync(0xffffffffu, sum, o);
                const float inv = 1.f / sum;
                for (int m = lane; m < mEnd; m += 32) sW[h][m] *= inv;
            }
        } else {
            // all logits NEG -> uniform softmax over the full row
            const float u = 1.f / (float)Ln;
            for (int m = t; m < Ln; m += 512) {
                sW[0][m] = u; sW[1][m] = u; sW[2][m] = u; sW[3][m] = u;
            }
        }
        __syncthreads();

        // ---- pass 3: weighted sum over values ----
        float4 acc = make_float4(0.f, 0.f, 0.f, 0.f);
        #pragma unroll 2
        for (int m0 = 0; m0 < mEnd; m0 += 8) {
            const int m = m0 + msub;
            if (m < mEnd) {
                const float  a   = sW[head][m];
                const size_t off = (rowBase + (size_t)m) * 64 + qd;
                const float4 x = tV[off];
                const float4 y = dV[off];
                const float4 v = Vc4[(size_t)(b * Ln + m) * 64 + qd];
                acc.x += a * (x.x + y.x + v.x);
                acc.y += a * (x.y + y.y + v.y);
                acc.z += a * (x.z + y.z + v.z);
                acc.w += a * (x.w + y.w + v.w);
            }
        }
        sRed[msub][qd] = acc;
        __syncthreads();
        if (msub == 0) {
            float4 o = sRed[0][qd];
            #pragma unroll
            for (int r = 1; r < 8; ++r) {
                const float4 rv = sRed[r][qd];
                o.x += rv.x; o.y += rv.y; o.z += rv.z; o.w += rv.w;
            }
            out[(size_t)(b * Ln + l) * 64 + qd] = o;
        }
        __syncthreads();   // protect smem reuse for second row
    }
}

// ---------------------------------------------------------------------------
extern "C" void kernel_launch(void* const* d_in, const int* in_sizes, int n_in,
                              void* d_out, int out_size)
{
    const float* queries = (const float*)d_in[0];
    const float* keys    = (const float*)d_in[1];
    const float4* tK     = (const float4*)d_in[2];
    const float4* tV     = (const float4*)d_in[3];
    const float4* dK     = (const float4*)d_in[4];
    const float4* dV     = (const float4*)d_in[5];
    const float* apK     = (const float*)d_in[6];
    const float* apV     = (const float*)d_in[7];
    const float* Qw      = (const float*)d_in[8];
    const float* Qb      = (const float*)d_in[9];
    const float* Kw      = (const float*)d_in[10];
    const float* Kb      = (const float*)d_in[11];
    const float* Vw      = (const float*)d_in[12];
    const float* Vb      = (const float*)d_in[13];
    const unsigned char* time_mask = (const unsigned char*)d_in[14];

    proj_kernel<<<(Bn * Ln) / PROJ_ROWS, 256>>>(queries, keys, apK, apV,
                                                Qw, Qb, Kw, Kb, Vw, Vb);
    attn_kernel<<<(Bn * Ln) / 2, 512>>>(tK, tV, dK, dV, time_mask, (float4*)d_out);
}